// round 11
// baseline (speedup 1.0000x reference)
#include <cuda_runtime.h>
#include <cstdint>

#define B          64
#define CROP       64
#define MAXN       196
#define KNBR       6
#define NSCORE     (3*CROP*CROP)        // 12288
#define WB         247
#define WS         18
#define TC         1024                 // main kernel threads
#define TN         256                  // nn kernel threads
#define NIT        (NSCORE/TC)          // 12
#define NWARP      (TC/32)              // 32
#define GPITCH     72                   // padded gray pitch (64 + 2*4)

typedef unsigned long long ull;

// output layout (f32, concatenated flattened tuple)
#define O_NODES 0
#define O_EI    62720
#define O_EF    213248
#define O_BI    439040
#define O_NV    451584
#define O_EV    464128
#define N_EDGE_TOT 75264                // B*196*6

__device__ float2 g_xy [B * MAXN];
__device__ int    g_val[B * MAXN];
__device__ int    g_flag[B];

__device__ __forceinline__ float score_of(float r) {
    float m = fabsf(r);
    return (m > 0.1f) ? m : -1.0f;
}
__device__ __forceinline__ unsigned enc_f(float s) {
    unsigned b = __float_as_uint(s);
    return (b & 0x80000000u) ? ~b : (b | 0x80000000u);
}

// 4 consecutive outputs (one row) of a KxK SAME conv on the zero-padded gray.
template<int K, int PAD, int WOFF>
__device__ __forceinline__ float4 conv_quad(const float* __restrict__ s_gpad,
                                            const float* __restrict__ s_w,
                                            int y, int x0)
{
    float a0 = 0.f, a1 = 0.f, a2 = 0.f, a3 = 0.f;
    #pragma unroll
    for (int dy = 0; dy < K; dy++) {
        const float* gr = s_gpad + (y + dy - PAD + 4)*GPITCH + (x0 - PAD + 4);
        float gv[K + 3];
        #pragma unroll
        for (int i = 0; i < K + 3; i++) gv[i] = gr[i];
        const float* wr = s_w + WOFF + dy*K;
        #pragma unroll
        for (int dx = 0; dx < K; dx++) {
            float w = wr[dx];
            a0 = fmaf(gv[dx],     w, a0);
            a1 = fmaf(gv[dx + 1], w, a1);
            a2 = fmaf(gv[dx + 2], w, a2);
            a3 = fmaf(gv[dx + 3], w, a3);
        }
    }
    return make_float4(a0, a1, a2, a3);
}

// smem layout offsets (bytes) for main_kernel
#define SM_SEL    0        // 256 ull
#define SM_WHIST  2048     // 32*256 u32
#define SM_PART   34816    // 1024 int
#define SM_RESP   38912    // 12288 f32
#define SM_GPAD   88064    // 5184 f32
#define SM_WIN    108800   // 972 f32
#define SM_W      112688   // 115 f32
#define SM_SCAN   113148   // 385 int
#define SM_WC     114688   // 384 int
#define SM_WS     116224   // 32 int
#define SM_TOTAL  116352

// ============================================================
// Kernel 1 (fused): crop+gray+conv -> top-k select -> nodes.  grid = 64
// ============================================================
__global__ void __launch_bounds__(TC, 1)
main_kernel(const float* __restrict__ img,
            const float* __restrict__ w1,
            const float* __restrict__ w2,
            const float* __restrict__ w3,
            float* __restrict__ out)
{
    extern __shared__ unsigned char dsm[];
    ull*      s_sel   = (ull*)(dsm + SM_SEL);
    unsigned* s_whist = (unsigned*)(dsm + SM_WHIST);
    int*      s_part  = (int*)(dsm + SM_PART);
    float*    s_resp  = (float*)(dsm + SM_RESP);
    float*    s_gpad  = (float*)(dsm + SM_GPAD);
    float*    s_win   = (float*)(dsm + SM_WIN);
    float*    s_w     = (float*)(dsm + SM_W);
    int*      s_scan  = (int*)(dsm + SM_SCAN);
    int*      s_wc    = (int*)(dsm + SM_WC);
    int*      s_ws    = (int*)(dsm + SM_WS);
    __shared__ unsigned s_pref;
    __shared__ int s_rem;

    const int b = blockIdx.x;
    const int t = threadIdx.x;
    const int lane = t & 31, warp = t >> 5;
    const float REC3 = __uint_as_float(0x3EAAAAABu);      // f32(1/3)

    // ---- PDL: reset this batch's flag, make it visible, then allow the
    //      dependent nn_kernel grid to launch (it spin-waits on the flag).
    if (t == 0) {
        asm volatile("st.relaxed.gpu.s32 [%0], %1;" :: "l"(&g_flag[b]), "r"(0) : "memory");
        __threadfence();
        cudaTriggerProgrammaticLaunchCompletion();
    }

    // ---- load weights + window, zero padded gray ----
    if (t < 9)  s_w[t]      = w1[t];
    if (t < 25) s_w[9 + t]  = w2[t];
    if (t < 81) s_w[34 + t] = w3[t];
    if (t < 3*WS*WS) {
        int c = t / (WS*WS);
        int r = (t % (WS*WS)) / WS;
        int x = t % WS;
        s_win[t] = img[(((size_t)b*3 + c)*512 + (WB + r))*512 + (WB + x)];
    }
    for (int i = t; i < GPITCH*GPITCH; i += TC) s_gpad[i] = 0.0f;
    __syncthreads();

    // ---- crop (bilinear) + gray mean: 4 px per thread ----
    #pragma unroll
    for (int g = 0; g < 4; g++) {
        int p = g*TC + t;
        int iy = p >> 6, ix = p & 63;
        float bx = __fsub_rn(__fmul_rn((float)ix + 0.5f, 0.03125f), 1.0f);
        float by = __fsub_rn(__fmul_rn((float)iy + 0.5f, 0.03125f), 1.0f);
        float px = __fsub_rn(__fmul_rn(__fadd_rn(__fmul_rn(bx, 0.03125f), 1.0f), 256.0f), 0.5f);
        float py = __fsub_rn(__fmul_rn(__fadd_rn(__fmul_rn(by, 0.03125f), 1.0f), 256.0f), 0.5f);
        int ix0 = (int)floorf(px), iy0 = (int)floorf(py);
        float fx = __fsub_rn(px, (float)ix0);
        float fy = __fsub_rn(py, (float)iy0);
        float wx0 = __fsub_rn(1.0f, fx);
        float wy0 = __fsub_rn(1.0f, fy);
        int lx0 = ix0 - WB, ly0 = iy0 - WB;
        float sum = 0.0f;
        #pragma unroll
        for (int c = 0; c < 3; c++) {
            const float* wc = s_win + c*WS*WS;
            float v00 = wc[ly0*WS + lx0],     v01 = wc[ly0*WS + lx0 + 1];
            float v10 = wc[(ly0+1)*WS + lx0], v11 = wc[(ly0+1)*WS + lx0 + 1];
            float tx0 = __fadd_rn(__fmul_rn(v00, wx0), __fmul_rn(v01, fx));
            float tx1 = __fadd_rn(__fmul_rn(v10, wx0), __fmul_rn(v11, fx));
            float v   = __fadd_rn(__fmul_rn(tx0, wy0), __fmul_rn(tx1, fy));
            sum = __fadd_rn(sum, v);
        }
        s_gpad[(iy + 4)*GPITCH + ix + 4] = __fmul_rn(sum, REC3);
    }
    __syncthreads();

    // ---- 3 DoG convs: each thread does one 4-wide quad per channel ----
    {
        int y  = t >> 4;
        int x0 = (t & 15) * 4;
        float4* rq = (float4*)s_resp;
        rq[t]          = conv_quad<3, 1, 0 >(s_gpad, s_w, y, x0);
        rq[1024 + t]   = conv_quad<5, 2, 9 >(s_gpad, s_w, y, x0);
        rq[2048 + t]   = conv_quad<9, 4, 34>(s_gpad, s_w, y, x0);
    }
    if (t == 0) { s_pref = 0; s_rem = MAXN; }
    __syncthreads();

    // ---- encode keys (linear it*TC + t layout) ----
    unsigned u[NIT];
    #pragma unroll
    for (int it = 0; it < NIT; it++)
        u[it] = enc_f(score_of(s_resp[it*TC + t]));

    // ---- radix select, 4 passes, zero atomics ----
    for (int pass = 0; pass < 4; pass++) {
        const int shift = 24 - 8*pass;
        {
            uint4* wz = (uint4*)s_whist;
            wz[t]        = make_uint4(0,0,0,0);
            wz[TC + t]   = make_uint4(0,0,0,0);
        }
        __syncthreads();
        const unsigned pref = s_pref;
        const int rem = s_rem;
        unsigned* wh = s_whist + warp*256;
        #pragma unroll
        for (int it = 0; it < NIT; it++) {
            unsigned uu = u[it];
            bool ok = (pass == 0) || ((uu >> (shift + 8)) == (pref >> (shift + 8)));
            unsigned active = __ballot_sync(0xffffffffu, ok);
            if (ok) {
                unsigned bin = (uu >> shift) & 255u;
                unsigned mset = __match_any_sync(active, bin);
                if (lane == __ffs(mset) - 1)
                    wh[bin] += __popc(mset);
            }
        }
        __syncthreads();
        // two-level hist reduce: all 1024 threads
        {
            int bin = t & 255, grp = t >> 8;
            int v = 0;
            #pragma unroll
            for (int w = 0; w < 8; w++)
                v += (int)s_whist[(grp*8 + w)*256 + bin];
            s_part[grp*256 + bin] = v;
        }
        __syncthreads();
        int v = 0;
        if (t < 256) {
            v = s_part[t] + s_part[256 + t] + s_part[512 + t] + s_part[768 + t];
            #pragma unroll
            for (int off = 1; off < 32; off <<= 1) {
                int o = __shfl_down_sync(0xffffffffu, v, off);
                if (lane + off < 32) v += o;
            }
            if (lane == 0) s_ws[warp] = v;
        }
        __syncthreads();
        if (t < 8) {
            int wv = s_ws[t];
            #pragma unroll
            for (int off = 1; off < 8; off <<= 1) {
                int o = __shfl_down_sync(0xFFu, wv, off);
                if (t + off < 8) wv += o;
            }
            s_ws[t] = wv;
        }
        __syncthreads();
        if (t < 256)
            s_scan[t] = v + ((warp < 7) ? s_ws[warp + 1] : 0);   // suffix sums
        __syncthreads();
        if (t < 256) {
            int Sd  = s_scan[t];
            int Sd1 = (t == 255) ? 0 : s_scan[t + 1];
            if (Sd >= rem && Sd1 < rem) {
                s_pref = pref | ((unsigned)t << shift);
                s_rem  = rem - Sd1;
            }
        }
        __syncthreads();
    }
    const unsigned u_t = s_pref;
    const int ktie = s_rem;

    // ---- compaction: packed (greater<<16 | tie) ballot prefix-scan ----
    #pragma unroll
    for (int it = 0; it < NIT; it++) {
        unsigned bg = __ballot_sync(0xffffffffu, u[it] > u_t);
        unsigned bt = __ballot_sync(0xffffffffu, u[it] == u_t);
        if (lane == 0) s_wc[it*NWARP + warp] = (__popc(bg) << 16) | __popc(bt);
    }
    __syncthreads();
    if (t < 384) {
        int v = s_wc[t];
        #pragma unroll
        for (int off = 1; off < 32; off <<= 1) {
            int o = __shfl_up_sync(0xffffffffu, v, off);
            if (lane >= off) v += o;
        }
        s_scan[t] = v;
        if (lane == 31) s_ws[warp] = v;
    }
    __syncthreads();
    if (t < 12) {
        int wv = s_ws[t];
        #pragma unroll
        for (int off = 1; off < 16; off <<= 1) {
            int o = __shfl_up_sync(0xFFFu, wv, off);
            if (t >= off) wv += o;
        }
        s_ws[t] = wv;
    }
    __syncthreads();
    const int cG = s_ws[11] >> 16;
    #pragma unroll
    for (int it = 0; it < NIT; it++) {
        unsigned uu = u[it];
        bool g = (uu > u_t), e = (uu == u_t);
        unsigned bg = __ballot_sync(0xffffffffu, g);
        unsigned bt = __ballot_sync(0xffffffffu, e);
        int cw = it*NWARP + warp;
        int widx = cw >> 5;
        int incl = s_scan[cw] + ((widx > 0) ? s_ws[widx - 1] : 0);
        int excl = incl - ((__popc(bg) << 16) | __popc(bt));
        unsigned below = (1u << lane) - 1u;
        if (g) {
            int rank = (excl >> 16) + __popc(bg & below);
            s_sel[rank] = (((ull)uu) << 32) | (unsigned)(~(unsigned)(it*TC + t));
        }
        if (e) {
            int rank = (excl & 0xFFFF) + __popc(bt & below);
            if (rank < ktie)
                s_sel[cG + rank] = (((ull)u_t) << 32) | (unsigned)(~(unsigned)(it*TC + t));
        }
    }
    if (t >= MAXN && t < 256) s_sel[t] = 0ULL;
    __syncthreads();

    // ---- bitonic sort 256 keys descending ----
    ull k = (t < 256) ? s_sel[t] : 0ULL;
    if (t < 256) {
        #pragma unroll
        for (int kk = 2; kk <= 32; kk <<= 1) {
            #pragma unroll
            for (int j = kk >> 1; j > 0; j >>= 1) {
                ull o = __shfl_xor_sync(0xffffffffu, k, j);
                bool takeMax = (((t & kk) == 0) != ((t & j) != 0));
                k = takeMax ? (k > o ? k : o) : (k < o ? k : o);
            }
        }
    }
    #pragma unroll
    for (int kk = 64; kk <= 256; kk <<= 1) {
        for (int j = kk >> 1; j >= 32; j >>= 1) {
            __syncthreads();
            if (t < 256) s_sel[t] = k;
            __syncthreads();
            if (t < 256) {
                ull o = s_sel[t ^ j];
                bool takeMax = (((t & kk) == 0) != ((t & j) != 0));
                k = takeMax ? (k > o ? k : o) : (k < o ? k : o);
            }
        }
        if (t < 256) {
            #pragma unroll
            for (int j = 16; j > 0; j >>= 1) {
                ull o = __shfl_xor_sync(0xffffffffu, k, j);
                bool takeMax = (((t & kk) == 0) != ((t & j) != 0));
                k = takeMax ? (k > o ? k : o) : (k < o ? k : o);
            }
        }
    }

    // ---- node features + export (x, y, valid) for the NN kernel ----
    const float REC63x2 = __uint_as_float(0x3D020821u);  // f32(1/63)*2
    if (t < MAXN) {
        unsigned idx = ~((unsigned)k);
        float rv = s_resp[idx];
        bool valid = (fabsf(rv) > 0.1f);
        int c  = idx >> 12;
        int rem2 = idx & 4095;
        int yi = rem2 >> 6, xi = rem2 & 63;
        float xc = __fsub_rn(__fmul_rn((float)xi, REC63x2), 1.0f);
        float yc = __fsub_rn(__fmul_rn((float)yi, REC63x2), 1.0f);
        float ecc = __fsqrt_rn(__fadd_rn(__fmul_rn(xc, xc), __fmul_rn(yc, yc)));
        float pol = (rv > 0.0f) ? 1.0f : ((rv < 0.0f) ? -1.0f : 0.0f);
        float vf = valid ? 1.0f : 0.0f;
        float* nrow = out + O_NODES + ((size_t)b*MAXN + t)*5;
        nrow[0] = xc * vf;
        nrow[1] = yc * vf;
        nrow[2] = pol * vf;
        nrow[3] = (float)c * vf;
        nrow[4] = ecc * vf;
        g_xy [b*MAXN + t] = make_float2(xc * vf, yc * vf);
        g_val[b*MAXN + t] = valid ? 1 : 0;
        out[O_NV + b*MAXN + t] = vf;
        out[O_BI + b*MAXN + t] = (float)b;
    }

    // ---- release: publish this batch's nodes to the waiting nn blocks ----
    __syncthreads();
    if (t == 0)
        asm volatile("st.release.gpu.s32 [%0], %1;" :: "l"(&g_flag[b]), "r"(1) : "memory");
}

// ============================================================
// Kernel 2: 6-NN + edges, one warp per node.  grid = (64, 25)
// Launched with programmatic stream serialization: starts while
// main_kernel runs; per-batch ordering via acquire-spin on g_flag.
// ============================================================
__global__ void __launch_bounds__(TN)
nn_kernel(float* __restrict__ out)
{
    __shared__ float2 s_xy[MAXN];
    __shared__ int s_val[MAXN];

    const int b = blockIdx.x;
    const int t = threadIdx.x;
    const int lane = t & 31, warp = t >> 5;

    // ---- wait for main_kernel block b ----
    if (t == 0) {
        int f;
        do {
            asm volatile("ld.acquire.gpu.s32 %0, [%1];" : "=r"(f) : "l"(&g_flag[b]) : "memory");
            if (!f) __nanosleep(64);
        } while (!f);
    }
    __syncthreads();

    if (t < MAXN) {
        int v = g_val[b*MAXN + t];
        float2 xy = g_xy[b*MAXN + t];
        s_val[t] = v;
        // sentinel coords for invalid nodes: distance becomes inf, which sorts
        // after all real distances (like the reference's 1e9); those slots only
        // ever emit ev=0 -> all-zero outputs.
        s_xy[t] = v ? xy : make_float2(1e19f, 1e19f);
    }
    __syncthreads();

    const int node = blockIdx.y * (TN/32) + warp;
    if (node >= MAXN) return;

    const float2 p = s_xy[node];
    const int sv = s_val[node];

    // collect 7 raw keys (no validity branches)
    ull key[7];
    #pragma unroll
    for (int m = 0; m < 7; m++) {
        int j = lane + m*32;
        if (j < MAXN) {
            float2 pj = s_xy[j];
            float dx = __fsub_rn(p.x, pj.x);
            float dy = __fsub_rn(p.y, pj.y);
            float s2 = __fadd_rn(__fmul_rn(dx, dx), __fmul_rn(dy, dy));
            float d = (s2 > 0.0f) ? __fsqrt_rn(s2) : 0.0f;
            if (j == node) d = 1000000000.0f;
            key[m] = (((ull)__float_as_uint(d)) << 32) | (unsigned)j;
        } else {
            key[m] = 0xFFFFFFFF00000000ULL;   // sorts after everything real
        }
    }

    // odd-even transposition sort of 7 keys (21 CAS, provably sorting)
    #pragma unroll
    for (int r = 0; r < 7; r++) {
        #pragma unroll
        for (int i = (r & 1); i + 1 < 7; i += 2) {
            ull a = key[i], c = key[i+1];
            key[i]   = (a < c) ? a : c;
            key[i+1] = (a < c) ? c : a;
        }
    }

    // 6-round tournament: keys are unique among selectable entries
    ull res = 0xFFFFFFFFFFFFFFFFULL;
    #pragma unroll
    for (int q = 0; q < KNBR; q++) {
        ull h = key[0];
        #pragma unroll
        for (int off = 16; off > 0; off >>= 1) {
            ull o = __shfl_xor_sync(0xffffffffu, h, off);
            h = (o < h) ? o : h;
        }
        if (lane == q) res = h;
        if (key[0] == h) {
            #pragma unroll
            for (int r = 0; r < 6; r++) key[r] = key[r+1];
            key[6] = 0xFFFFFFFFFFFFFFFFULL;
        }
    }

    // lanes 0..5 emit edges (select-masked: sentinel-derived values never leak)
    if (lane < KNBR) {
        const float DIST_T = (float)(4.05 / 4.2);
        unsigned jd = (unsigned)res;
        float d = __uint_as_float((unsigned)(res >> 32));
        bool ev = (d < DIST_T) && (sv != 0);
        float2 pj = s_xy[jd];
        float dx = __fsub_rn(pj.x, p.x);
        float dy = __fsub_rn(pj.y, p.y);
        float s2 = __fadd_rn(__fmul_rn(dx, dx), __fmul_rn(dy, dy));
        float cd = (s2 > 0.0f) ? __fsqrt_rn(s2) : 0.0f;
        size_t e = ((size_t)b*MAXN + node)*KNBR + lane;
        out[O_EI + e]              = ev ? (float)(b*MAXN + node) : 0.0f;
        out[O_EI + N_EDGE_TOT + e] = ev ? (float)(b*MAXN + jd)   : 0.0f;
        out[O_EF + e*3 + 0] = ev ? dx : 0.0f;
        out[O_EF + e*3 + 1] = ev ? dy : 0.0f;
        out[O_EF + e*3 + 2] = ev ? cd : 0.0f;
        out[O_EV + e] = ev ? 1.0f : 0.0f;
    }
}

extern "C" void kernel_launch(void* const* d_in, const int* in_sizes, int n_in,
                              void* d_out, int out_size)
{
    const float* img = (const float*)d_in[0];
    const float* w1  = (const float*)d_in[1];
    const float* w2  = (const float*)d_in[2];
    const float* w3  = (const float*)d_in[3];
    float* out = (float*)d_out;

    cudaFuncSetAttribute(main_kernel,
                         cudaFuncAttributeMaxDynamicSharedMemorySize, SM_TOTAL);
    main_kernel<<<B, TC, SM_TOTAL>>>(img, w1, w2, w3, out);

    // nn_kernel with programmatic stream serialization: may start while
    // main_kernel is still running (after all its blocks triggered).
    cudaLaunchConfig_t cfg = {};
    cfg.gridDim  = dim3(B, (MAXN + TN/32 - 1) / (TN/32), 1);
    cfg.blockDim = dim3(TN, 1, 1);
    cfg.dynamicSmemBytes = 0;
    cfg.stream = 0;
    cudaLaunchAttribute attrs[1];
    attrs[0].id = cudaLaunchAttributeProgrammaticStreamSerialization;
    attrs[0].val.programmaticStreamSerializationAllowed = 1;
    cfg.attrs = attrs;
    cfg.numAttrs = 1;
    cudaLaunchKernelEx(&cfg, nn_kernel, out);
}

// round 12
// speedup vs baseline: 1.0621x; 1.0621x over previous
#include <cuda_runtime.h>
#include <cstdint>

#define B          64
#define CROP       64
#define MAXN       196
#define KNBR       6
#define NSCORE     (3*CROP*CROP)        // 12288
#define WB         247
#define WS         18
#define TC         1024                 // main kernel threads
#define TN         512                  // nn kernel threads (16 warps)
#define NIT        (NSCORE/TC)          // 12
#define NWARP      (TC/32)              // 32
#define GPITCH     72                   // padded gray pitch (64 + 2*4)

typedef unsigned long long ull;

// output layout (f32, concatenated flattened tuple)
#define O_NODES 0
#define O_EI    62720
#define O_EF    213248
#define O_BI    439040
#define O_NV    451584
#define O_EV    464128
#define N_EDGE_TOT 75264                // B*196*6

__device__ float2 g_xy [B * MAXN];
__device__ int    g_val[B * MAXN];

__device__ __forceinline__ float score_of(float r) {
    float m = fabsf(r);
    return (m > 0.1f) ? m : -1.0f;
}
__device__ __forceinline__ unsigned enc_f(float s) {
    unsigned b = __float_as_uint(s);
    return (b & 0x80000000u) ? ~b : (b | 0x80000000u);
}

// 4 consecutive outputs (one row) of a KxK SAME conv on the zero-padded gray.
template<int K, int PAD, int WOFF>
__device__ __forceinline__ float4 conv_quad(const float* __restrict__ s_gpad,
                                            const float* __restrict__ s_w,
                                            int y, int x0)
{
    float a0 = 0.f, a1 = 0.f, a2 = 0.f, a3 = 0.f;
    #pragma unroll
    for (int dy = 0; dy < K; dy++) {
        const float* gr = s_gpad + (y + dy - PAD + 4)*GPITCH + (x0 - PAD + 4);
        float gv[K + 3];
        #pragma unroll
        for (int i = 0; i < K + 3; i++) gv[i] = gr[i];
        const float* wr = s_w + WOFF + dy*K;
        #pragma unroll
        for (int dx = 0; dx < K; dx++) {
            float w = wr[dx];
            a0 = fmaf(gv[dx],     w, a0);
            a1 = fmaf(gv[dx + 1], w, a1);
            a2 = fmaf(gv[dx + 2], w, a2);
            a3 = fmaf(gv[dx + 3], w, a3);
        }
    }
    return make_float4(a0, a1, a2, a3);
}

// smem layout offsets (bytes) for main_kernel
#define SM_SEL    0        // 256 ull
#define SM_WHIST  2048     // 32*256 u32
#define SM_PART   34816    // 1024 int
#define SM_RESP   38912    // 12288 f32
#define SM_GPAD   88064    // 5184 f32
#define SM_WIN    108800   // 972 f32
#define SM_W      112688   // 115 f32
#define SM_SCAN   113148   // 385 int
#define SM_WC     114688   // 384 int
#define SM_WS     116224   // 32 int
#define SM_TOTAL  116352

// ============================================================
// Kernel 1 (fused): crop+gray+conv -> top-k select -> nodes.  grid = 64
// ============================================================
__global__ void __launch_bounds__(TC, 1)
main_kernel(const float* __restrict__ img,
            const float* __restrict__ w1,
            const float* __restrict__ w2,
            const float* __restrict__ w3,
            float* __restrict__ out)
{
    extern __shared__ unsigned char dsm[];
    ull*      s_sel   = (ull*)(dsm + SM_SEL);
    unsigned* s_whist = (unsigned*)(dsm + SM_WHIST);
    int*      s_part  = (int*)(dsm + SM_PART);
    float*    s_resp  = (float*)(dsm + SM_RESP);
    float*    s_gpad  = (float*)(dsm + SM_GPAD);
    float*    s_win   = (float*)(dsm + SM_WIN);
    float*    s_w     = (float*)(dsm + SM_W);
    int*      s_scan  = (int*)(dsm + SM_SCAN);
    int*      s_wc    = (int*)(dsm + SM_WC);
    int*      s_ws    = (int*)(dsm + SM_WS);
    __shared__ unsigned s_pref;
    __shared__ int s_rem;

    const int b = blockIdx.x;
    const int t = threadIdx.x;
    const int lane = t & 31, warp = t >> 5;
    const float REC3 = __uint_as_float(0x3EAAAAABu);      // f32(1/3)

    // ---- load weights + window, zero padded gray ----
    if (t < 9)  s_w[t]      = w1[t];
    if (t < 25) s_w[9 + t]  = w2[t];
    if (t < 81) s_w[34 + t] = w3[t];
    if (t < 3*WS*WS) {
        int c = t / (WS*WS);
        int r = (t % (WS*WS)) / WS;
        int x = t % WS;
        s_win[t] = img[(((size_t)b*3 + c)*512 + (WB + r))*512 + (WB + x)];
    }
    for (int i = t; i < GPITCH*GPITCH; i += TC) s_gpad[i] = 0.0f;
    __syncthreads();

    // ---- crop (bilinear) + gray mean: 4 px per thread ----
    #pragma unroll
    for (int g = 0; g < 4; g++) {
        int p = g*TC + t;
        int iy = p >> 6, ix = p & 63;
        float bx = __fsub_rn(__fmul_rn((float)ix + 0.5f, 0.03125f), 1.0f);
        float by = __fsub_rn(__fmul_rn((float)iy + 0.5f, 0.03125f), 1.0f);
        float px = __fsub_rn(__fmul_rn(__fadd_rn(__fmul_rn(bx, 0.03125f), 1.0f), 256.0f), 0.5f);
        float py = __fsub_rn(__fmul_rn(__fadd_rn(__fmul_rn(by, 0.03125f), 1.0f), 256.0f), 0.5f);
        int ix0 = (int)floorf(px), iy0 = (int)floorf(py);
        float fx = __fsub_rn(px, (float)ix0);
        float fy = __fsub_rn(py, (float)iy0);
        float wx0 = __fsub_rn(1.0f, fx);
        float wy0 = __fsub_rn(1.0f, fy);
        int lx0 = ix0 - WB, ly0 = iy0 - WB;
        float sum = 0.0f;
        #pragma unroll
        for (int c = 0; c < 3; c++) {
            const float* wc = s_win + c*WS*WS;
            float v00 = wc[ly0*WS + lx0],     v01 = wc[ly0*WS + lx0 + 1];
            float v10 = wc[(ly0+1)*WS + lx0], v11 = wc[(ly0+1)*WS + lx0 + 1];
            float tx0 = __fadd_rn(__fmul_rn(v00, wx0), __fmul_rn(v01, fx));
            float tx1 = __fadd_rn(__fmul_rn(v10, wx0), __fmul_rn(v11, fx));
            float v   = __fadd_rn(__fmul_rn(tx0, wy0), __fmul_rn(tx1, fy));
            sum = __fadd_rn(sum, v);
        }
        s_gpad[(iy + 4)*GPITCH + ix + 4] = __fmul_rn(sum, REC3);
    }
    __syncthreads();

    // ---- 3 DoG convs: each thread does one 4-wide quad per channel ----
    {
        int y  = t >> 4;
        int x0 = (t & 15) * 4;
        float4* rq = (float4*)s_resp;
        rq[t]          = conv_quad<3, 1, 0 >(s_gpad, s_w, y, x0);
        rq[1024 + t]   = conv_quad<5, 2, 9 >(s_gpad, s_w, y, x0);
        rq[2048 + t]   = conv_quad<9, 4, 34>(s_gpad, s_w, y, x0);
    }
    if (t == 0) { s_pref = 0; s_rem = MAXN; }
    __syncthreads();

    // ---- encode keys (linear it*TC + t layout) ----
    unsigned u[NIT];
    #pragma unroll
    for (int it = 0; it < NIT; it++)
        u[it] = enc_f(score_of(s_resp[it*TC + t]));

    // ---- radix select, 4 passes, zero atomics ----
    for (int pass = 0; pass < 4; pass++) {
        const int shift = 24 - 8*pass;
        {
            uint4* wz = (uint4*)s_whist;
            wz[t]        = make_uint4(0,0,0,0);
            wz[TC + t]   = make_uint4(0,0,0,0);
        }
        __syncthreads();
        const unsigned pref = s_pref;
        const int rem = s_rem;
        unsigned* wh = s_whist + warp*256;
        #pragma unroll
        for (int it = 0; it < NIT; it++) {
            unsigned uu = u[it];
            bool ok = (pass == 0) || ((uu >> (shift + 8)) == (pref >> (shift + 8)));
            unsigned active = __ballot_sync(0xffffffffu, ok);
            if (ok) {
                unsigned bin = (uu >> shift) & 255u;
                unsigned mset = __match_any_sync(active, bin);
                if (lane == __ffs(mset) - 1)
                    wh[bin] += __popc(mset);
            }
        }
        __syncthreads();
        // two-level hist reduce: all 1024 threads
        {
            int bin = t & 255, grp = t >> 8;
            int v = 0;
            #pragma unroll
            for (int w = 0; w < 8; w++)
                v += (int)s_whist[(grp*8 + w)*256 + bin];
            s_part[grp*256 + bin] = v;
        }
        __syncthreads();
        int v = 0;
        if (t < 256) {
            v = s_part[t] + s_part[256 + t] + s_part[512 + t] + s_part[768 + t];
            #pragma unroll
            for (int off = 1; off < 32; off <<= 1) {
                int o = __shfl_down_sync(0xffffffffu, v, off);
                if (lane + off < 32) v += o;
            }
            if (lane == 0) s_ws[warp] = v;
        }
        __syncthreads();
        if (t < 8) {
            int wv = s_ws[t];
            #pragma unroll
            for (int off = 1; off < 8; off <<= 1) {
                int o = __shfl_down_sync(0xFFu, wv, off);
                if (t + off < 8) wv += o;
            }
            s_ws[t] = wv;
        }
        __syncthreads();
        if (t < 256)
            s_scan[t] = v + ((warp < 7) ? s_ws[warp + 1] : 0);   // suffix sums
        __syncthreads();
        if (t < 256) {
            int Sd  = s_scan[t];
            int Sd1 = (t == 255) ? 0 : s_scan[t + 1];
            if (Sd >= rem && Sd1 < rem) {
                s_pref = pref | ((unsigned)t << shift);
                s_rem  = rem - Sd1;
            }
        }
        __syncthreads();
    }
    const unsigned u_t = s_pref;
    const int ktie = s_rem;

    // ---- compaction: packed (greater<<16 | tie) ballot prefix-scan ----
    #pragma unroll
    for (int it = 0; it < NIT; it++) {
        unsigned bg = __ballot_sync(0xffffffffu, u[it] > u_t);
        unsigned bt = __ballot_sync(0xffffffffu, u[it] == u_t);
        if (lane == 0) s_wc[it*NWARP + warp] = (__popc(bg) << 16) | __popc(bt);
    }
    __syncthreads();
    if (t < 384) {
        int v = s_wc[t];
        #pragma unroll
        for (int off = 1; off < 32; off <<= 1) {
            int o = __shfl_up_sync(0xffffffffu, v, off);
            if (lane >= off) v += o;
        }
        s_scan[t] = v;
        if (lane == 31) s_ws[warp] = v;
    }
    __syncthreads();
    if (t < 12) {
        int wv = s_ws[t];
        #pragma unroll
        for (int off = 1; off < 16; off <<= 1) {
            int o = __shfl_up_sync(0xFFFu, wv, off);
            if (t >= off) wv += o;
        }
        s_ws[t] = wv;
    }
    __syncthreads();
    const int cG = s_ws[11] >> 16;
    #pragma unroll
    for (int it = 0; it < NIT; it++) {
        unsigned uu = u[it];
        bool g = (uu > u_t), e = (uu == u_t);
        unsigned bg = __ballot_sync(0xffffffffu, g);
        unsigned bt = __ballot_sync(0xffffffffu, e);
        int cw = it*NWARP + warp;
        int widx = cw >> 5;
        int incl = s_scan[cw] + ((widx > 0) ? s_ws[widx - 1] : 0);
        int excl = incl - ((__popc(bg) << 16) | __popc(bt));
        unsigned below = (1u << lane) - 1u;
        if (g) {
            int rank = (excl >> 16) + __popc(bg & below);
            s_sel[rank] = (((ull)uu) << 32) | (unsigned)(~(unsigned)(it*TC + t));
        }
        if (e) {
            int rank = (excl & 0xFFFF) + __popc(bt & below);
            if (rank < ktie)
                s_sel[cG + rank] = (((ull)u_t) << 32) | (unsigned)(~(unsigned)(it*TC + t));
        }
    }
    if (t >= MAXN && t < 256) s_sel[t] = 0ULL;
    __syncthreads();

    // ---- bitonic sort 256 keys descending ----
    ull k = (t < 256) ? s_sel[t] : 0ULL;
    if (t < 256) {
        #pragma unroll
        for (int kk = 2; kk <= 32; kk <<= 1) {
            #pragma unroll
            for (int j = kk >> 1; j > 0; j >>= 1) {
                ull o = __shfl_xor_sync(0xffffffffu, k, j);
                bool takeMax = (((t & kk) == 0) != ((t & j) != 0));
                k = takeMax ? (k > o ? k : o) : (k < o ? k : o);
            }
        }
    }
    #pragma unroll
    for (int kk = 64; kk <= 256; kk <<= 1) {
        for (int j = kk >> 1; j >= 32; j >>= 1) {
            __syncthreads();
            if (t < 256) s_sel[t] = k;
            __syncthreads();
            if (t < 256) {
                ull o = s_sel[t ^ j];
                bool takeMax = (((t & kk) == 0) != ((t & j) != 0));
                k = takeMax ? (k > o ? k : o) : (k < o ? k : o);
            }
        }
        if (t < 256) {
            #pragma unroll
            for (int j = 16; j > 0; j >>= 1) {
                ull o = __shfl_xor_sync(0xffffffffu, k, j);
                bool takeMax = (((t & kk) == 0) != ((t & j) != 0));
                k = takeMax ? (k > o ? k : o) : (k < o ? k : o);
            }
        }
    }

    // ---- node features + export (x, y, valid) for the NN kernel ----
    const float REC63x2 = __uint_as_float(0x3D020821u);  // f32(1/63)*2
    if (t < MAXN) {
        unsigned idx = ~((unsigned)k);
        float rv = s_resp[idx];
        bool valid = (fabsf(rv) > 0.1f);
        int c  = idx >> 12;
        int rem2 = idx & 4095;
        int yi = rem2 >> 6, xi = rem2 & 63;
        float xc = __fsub_rn(__fmul_rn((float)xi, REC63x2), 1.0f);
        float yc = __fsub_rn(__fmul_rn((float)yi, REC63x2), 1.0f);
        float ecc = __fsqrt_rn(__fadd_rn(__fmul_rn(xc, xc), __fmul_rn(yc, yc)));
        float pol = (rv > 0.0f) ? 1.0f : ((rv < 0.0f) ? -1.0f : 0.0f);
        float vf = valid ? 1.0f : 0.0f;
        float* nrow = out + O_NODES + ((size_t)b*MAXN + t)*5;
        nrow[0] = xc * vf;
        nrow[1] = yc * vf;
        nrow[2] = pol * vf;
        nrow[3] = (float)c * vf;
        nrow[4] = ecc * vf;
        g_xy [b*MAXN + t] = make_float2(xc * vf, yc * vf);
        g_val[b*MAXN + t] = valid ? 1 : 0;
        out[O_NV + b*MAXN + t] = vf;
        out[O_BI + b*MAXN + t] = (float)b;
    }
}

// ============================================================
// Kernel 2: 6-NN + edges, one warp per node.  grid = (64, 13), 512 thr
// ============================================================
__global__ void __launch_bounds__(TN)
nn_kernel(float* __restrict__ out)
{
    __shared__ float2 s_xy[MAXN];
    __shared__ int s_val[MAXN];

    const int b = blockIdx.x;
    const int t = threadIdx.x;
    const int lane = t & 31, warp = t >> 5;

    if (t < MAXN) {
        int v = g_val[b*MAXN + t];
        float2 xy = g_xy[b*MAXN + t];
        s_val[t] = v;
        // sentinel coords for invalid nodes: distance becomes inf, sorts after
        // all real distances (like the reference's 1e9); those slots only ever
        // emit ev=0 -> all-zero outputs.
        s_xy[t] = v ? xy : make_float2(1e19f, 1e19f);
    }
    __syncthreads();

    const int node = blockIdx.y * (TN/32) + warp;
    if (node >= MAXN) return;

    const float2 p = s_xy[node];
    const int sv = s_val[node];

    // collect 7 raw keys; m=0..5 always in-range (lane+160 <= 191 < 196)
    ull key[7];
    #pragma unroll
    for (int m = 0; m < 6; m++) {
        int j = lane + m*32;
        float2 pj = s_xy[j];
        float dx = __fsub_rn(p.x, pj.x);
        float dy = __fsub_rn(p.y, pj.y);
        float s2 = __fadd_rn(__fmul_rn(dx, dx), __fmul_rn(dy, dy));
        float d = (s2 > 0.0f) ? __fsqrt_rn(s2) : 0.0f;
        if (j == node) d = 1000000000.0f;
        key[m] = (((ull)__float_as_uint(d)) << 32) | (unsigned)j;
    }
    {
        int j = lane + 192;
        if (j < MAXN) {
            float2 pj = s_xy[j];
            float dx = __fsub_rn(p.x, pj.x);
            float dy = __fsub_rn(p.y, pj.y);
            float s2 = __fadd_rn(__fmul_rn(dx, dx), __fmul_rn(dy, dy));
            float d = (s2 > 0.0f) ? __fsqrt_rn(s2) : 0.0f;
            if (j == node) d = 1000000000.0f;
            key[6] = (((ull)__float_as_uint(d)) << 32) | (unsigned)j;
        } else {
            key[6] = 0xFFFFFFFF00000000ULL;   // sorts after everything real
        }
    }

    // odd-even transposition sort of 7 keys (21 CAS)
    #pragma unroll
    for (int r = 0; r < 7; r++) {
        #pragma unroll
        for (int i = (r & 1); i + 1 < 7; i += 2) {
            ull a = key[i], c = key[i+1];
            key[i]   = (a < c) ? a : c;
            key[i+1] = (a < c) ? c : a;
        }
    }

    // 6-round tournament, 32-bit reductions:
    // d >= 0 always -> d's float bits are monotone as unsigned ints
    // (sentinel hi=0xFFFFFFFF is the max). (d,j) lexicographic min =
    // int-min over d-bits, then int-min over j among d==dmin lanes.
    unsigned res_d = 0xFFFFFFFFu, res_j = 0;
    #pragma unroll
    for (int q = 0; q < KNBR; q++) {
        unsigned dh = (unsigned)(key[0] >> 32);
        unsigned jh = (unsigned)key[0];
        unsigned dmin = dh;
        #pragma unroll
        for (int off = 16; off > 0; off >>= 1) {
            unsigned o = __shfl_xor_sync(0xffffffffu, dmin, off);
            dmin = (o < dmin) ? o : dmin;
        }
        unsigned jm = (dh == dmin) ? jh : 0xFFFFFFFFu;
        #pragma unroll
        for (int off = 16; off > 0; off >>= 1) {
            unsigned o = __shfl_xor_sync(0xffffffffu, jm, off);
            jm = (o < jm) ? o : jm;
        }
        if (lane == q) { res_d = dmin; res_j = jm; }
        if (dh == dmin && jh == jm) {
            #pragma unroll
            for (int r = 0; r < 6; r++) key[r] = key[r+1];
            key[6] = 0xFFFFFFFFFFFFFFFFULL;
        }
    }

    // lanes 0..5 emit edges (select-masked: sentinel values never leak)
    if (lane < KNBR) {
        const float DIST_T = (float)(4.05 / 4.2);
        unsigned jd = res_j;
        float d = __uint_as_float(res_d);
        bool ev = (d < DIST_T) && (sv != 0);
        float2 pj = s_xy[jd];
        float dx = __fsub_rn(pj.x, p.x);
        float dy = __fsub_rn(pj.y, p.y);
        float s2 = __fadd_rn(__fmul_rn(dx, dx), __fmul_rn(dy, dy));
        float cd = (s2 > 0.0f) ? __fsqrt_rn(s2) : 0.0f;
        size_t e = ((size_t)b*MAXN + node)*KNBR + lane;
        out[O_EI + e]              = ev ? (float)(b*MAXN + node) : 0.0f;
        out[O_EI + N_EDGE_TOT + e] = ev ? (float)(b*MAXN + jd)   : 0.0f;
        out[O_EF + e*3 + 0] = ev ? dx : 0.0f;
        out[O_EF + e*3 + 1] = ev ? dy : 0.0f;
        out[O_EF + e*3 + 2] = ev ? cd : 0.0f;
        out[O_EV + e] = ev ? 1.0f : 0.0f;
    }
}

extern "C" void kernel_launch(void* const* d_in, const int* in_sizes, int n_in,
                              void* d_out, int out_size)
{
    const float* img = (const float*)d_in[0];
    const float* w1  = (const float*)d_in[1];
    const float* w2  = (const float*)d_in[2];
    const float* w3  = (const float*)d_in[3];
    float* out = (float*)d_out;

    cudaFuncSetAttribute(main_kernel,
                         cudaFuncAttributeMaxDynamicSharedMemorySize, SM_TOTAL);
    main_kernel<<<B, TC, SM_TOTAL>>>(img, w1, w2, w3, out);

    nn_kernel<<<dim3(B, (MAXN + TN/32 - 1) / (TN/32)), TN>>>(out);
}

// round 13
// speedup vs baseline: 1.2103x; 1.1395x over previous
#include <cuda_runtime.h>
#include <cstdint>

#define B          64
#define CROP       64
#define MAXN       196
#define KNBR       6
#define NSCORE     (3*CROP*CROP)        // 12288
#define WB         247
#define WS         18
#define TC         1024                 // main kernel threads
#define TN         512                  // nn kernel threads (16 warps)
#define NIT        (NSCORE/TC)          // 12
#define NWARP      (TC/32)              // 32
#define GPITCH     72                   // padded gray pitch (64 + 2*4)

typedef unsigned long long ull;

// output layout (f32, concatenated flattened tuple)
#define O_NODES 0
#define O_EI    62720
#define O_EF    213248
#define O_BI    439040
#define O_NV    451584
#define O_EV    464128
#define N_EDGE_TOT 75264                // B*196*6

__device__ float2 g_xy [B * MAXN];
__device__ int    g_val[B * MAXN];

__device__ __forceinline__ float score_of(float r) {
    float m = fabsf(r);
    return (m > 0.1f) ? m : -1.0f;
}
__device__ __forceinline__ unsigned enc_f(float s) {
    unsigned b = __float_as_uint(s);
    return (b & 0x80000000u) ? ~b : (b | 0x80000000u);
}

// 4 consecutive outputs (one row) of a KxK SAME conv on the zero-padded gray.
// float4 loads: base (row*72 + x0) is 16B-aligned; taps live in gv[4-PAD ..
// 4-PAD+K+2] <= gv[11]. Tap order (dy asc, dx asc) identical -> bit-exact.
template<int K, int PAD, int WOFF>
__device__ __forceinline__ float4 conv_quad(const float* __restrict__ s_gpad,
                                            const float* __restrict__ s_w,
                                            int y, int x0)
{
    float a0 = 0.f, a1 = 0.f, a2 = 0.f, a3 = 0.f;
    #pragma unroll
    for (int dy = 0; dy < K; dy++) {
        const float4* gr4 = reinterpret_cast<const float4*>(
            s_gpad + (y + dy - PAD + 4)*GPITCH + x0);
        float4 q0 = gr4[0], q1 = gr4[1], q2 = gr4[2];
        float gv[12] = {q0.x,q0.y,q0.z,q0.w, q1.x,q1.y,q1.z,q1.w,
                        q2.x,q2.y,q2.z,q2.w};
        const float* wr = s_w + WOFF + dy*K;
        #pragma unroll
        for (int dx = 0; dx < K; dx++) {
            float w = wr[dx];
            const int o = 4 - PAD + dx;
            a0 = fmaf(gv[o],     w, a0);
            a1 = fmaf(gv[o + 1], w, a1);
            a2 = fmaf(gv[o + 2], w, a2);
            a3 = fmaf(gv[o + 3], w, a3);
        }
    }
    return make_float4(a0, a1, a2, a3);
}

// smem layout offsets (bytes) for main_kernel
#define SM_SEL    0        // 256 ull
#define SM_WHIST  2048     // 32*256 u32
#define SM_PART   34816    // 1024 int
#define SM_RESP   38912    // 12288 f32
#define SM_GPAD   88064    // 5184 f32 (16B aligned)
#define SM_WIN    108800   // 972 f32
#define SM_W      112688   // 115 f32
#define SM_SCAN   113148   // 385 int
#define SM_WC     114688   // 384 int
#define SM_WS     116224   // 32 int
#define SM_TOTAL  116352

// ============================================================
// Kernel 1 (fused): crop+gray+conv -> top-k select -> nodes.  grid = 64
// ============================================================
__global__ void __launch_bounds__(TC, 1)
main_kernel(const float* __restrict__ img,
            const float* __restrict__ w1,
            const float* __restrict__ w2,
            const float* __restrict__ w3,
            float* __restrict__ out)
{
    extern __shared__ unsigned char dsm[];
    ull*      s_sel   = (ull*)(dsm + SM_SEL);
    unsigned* s_whist = (unsigned*)(dsm + SM_WHIST);
    int*      s_part  = (int*)(dsm + SM_PART);
    float*    s_resp  = (float*)(dsm + SM_RESP);
    float*    s_gpad  = (float*)(dsm + SM_GPAD);
    float*    s_win   = (float*)(dsm + SM_WIN);
    float*    s_w     = (float*)(dsm + SM_W);
    int*      s_scan  = (int*)(dsm + SM_SCAN);
    int*      s_wc    = (int*)(dsm + SM_WC);
    int*      s_ws    = (int*)(dsm + SM_WS);
    __shared__ unsigned s_pref;
    __shared__ int s_rem, s_tot;

    const int b = blockIdx.x;
    const int t = threadIdx.x;
    const int lane = t & 31, warp = t >> 5;
    const float REC3 = __uint_as_float(0x3EAAAAABu);      // f32(1/3)

    // ---- load weights + window, zero padded gray ----
    if (t < 9)  s_w[t]      = w1[t];
    if (t < 25) s_w[9 + t]  = w2[t];
    if (t < 81) s_w[34 + t] = w3[t];
    if (t < 3*WS*WS) {
        int c = t / (WS*WS);
        int r = (t % (WS*WS)) / WS;
        int x = t % WS;
        s_win[t] = img[(((size_t)b*3 + c)*512 + (WB + r))*512 + (WB + x)];
    }
    for (int i = t; i < GPITCH*GPITCH; i += TC) s_gpad[i] = 0.0f;
    __syncthreads();

    // ---- crop (bilinear) + gray mean: 4 px per thread ----
    #pragma unroll
    for (int g = 0; g < 4; g++) {
        int p = g*TC + t;
        int iy = p >> 6, ix = p & 63;
        float bx = __fsub_rn(__fmul_rn((float)ix + 0.5f, 0.03125f), 1.0f);
        float by = __fsub_rn(__fmul_rn((float)iy + 0.5f, 0.03125f), 1.0f);
        float px = __fsub_rn(__fmul_rn(__fadd_rn(__fmul_rn(bx, 0.03125f), 1.0f), 256.0f), 0.5f);
        float py = __fsub_rn(__fmul_rn(__fadd_rn(__fmul_rn(by, 0.03125f), 1.0f), 256.0f), 0.5f);
        int ix0 = (int)floorf(px), iy0 = (int)floorf(py);
        float fx = __fsub_rn(px, (float)ix0);
        float fy = __fsub_rn(py, (float)iy0);
        float wx0 = __fsub_rn(1.0f, fx);
        float wy0 = __fsub_rn(1.0f, fy);
        int lx0 = ix0 - WB, ly0 = iy0 - WB;
        float sum = 0.0f;
        #pragma unroll
        for (int c = 0; c < 3; c++) {
            const float* wc = s_win + c*WS*WS;
            float v00 = wc[ly0*WS + lx0],     v01 = wc[ly0*WS + lx0 + 1];
            float v10 = wc[(ly0+1)*WS + lx0], v11 = wc[(ly0+1)*WS + lx0 + 1];
            float tx0 = __fadd_rn(__fmul_rn(v00, wx0), __fmul_rn(v01, fx));
            float tx1 = __fadd_rn(__fmul_rn(v10, wx0), __fmul_rn(v11, fx));
            float v   = __fadd_rn(__fmul_rn(tx0, wy0), __fmul_rn(tx1, fy));
            sum = __fadd_rn(sum, v);
        }
        s_gpad[(iy + 4)*GPITCH + ix + 4] = __fmul_rn(sum, REC3);
    }
    __syncthreads();

    // ---- 3 DoG convs: each thread does one 4-wide quad per channel ----
    {
        int y  = t >> 4;
        int x0 = (t & 15) * 4;
        float4* rq = (float4*)s_resp;
        rq[t]          = conv_quad<3, 1, 0 >(s_gpad, s_w, y, x0);
        rq[1024 + t]   = conv_quad<5, 2, 9 >(s_gpad, s_w, y, x0);
        rq[2048 + t]   = conv_quad<9, 4, 34>(s_gpad, s_w, y, x0);
    }
    if (t == 0) { s_pref = 0; s_rem = MAXN; }
    __syncthreads();

    // ---- encode keys (linear it*TC + t layout) ----
    unsigned u[NIT];
    #pragma unroll
    for (int it = 0; it < NIT; it++)
        u[it] = enc_f(score_of(s_resp[it*TC + t]));

    // ---- radix select with early exit, zero atomics ----
    // Stops as soon as candidates-with-truncated-value >= boundary fit in 256:
    // then a single predicate collect + full-key bitonic gives exact top_k
    // order (value desc, index asc), ties included.
    int sh = -1;
    for (int pass = 0; pass < 4; pass++) {
        const int shift = 24 - 8*pass;
        {
            uint4* wz = (uint4*)s_whist;
            wz[t]        = make_uint4(0,0,0,0);
            wz[TC + t]   = make_uint4(0,0,0,0);
        }
        __syncthreads();
        const unsigned pref = s_pref;
        const int rem = s_rem;
        unsigned* wh = s_whist + warp*256;
        #pragma unroll
        for (int it = 0; it < NIT; it++) {
            unsigned uu = u[it];
            bool ok = (pass == 0) || ((uu >> (shift + 8)) == (pref >> (shift + 8)));
            unsigned active = __ballot_sync(0xffffffffu, ok);
            if (ok) {
                unsigned bin = (uu >> shift) & 255u;
                unsigned mset = __match_any_sync(active, bin);
                if (lane == __ffs(mset) - 1)
                    wh[bin] += __popc(mset);
            }
        }
        __syncthreads();
        // two-level hist reduce: all 1024 threads
        {
            int bin = t & 255, grp = t >> 8;
            int v = 0;
            #pragma unroll
            for (int w = 0; w < 8; w++)
                v += (int)s_whist[(grp*8 + w)*256 + bin];
            s_part[grp*256 + bin] = v;
        }
        __syncthreads();
        int v = 0;
        if (t < 256) {
            v = s_part[t] + s_part[256 + t] + s_part[512 + t] + s_part[768 + t];
            #pragma unroll
            for (int off = 1; off < 32; off <<= 1) {
                int o = __shfl_down_sync(0xffffffffu, v, off);
                if (lane + off < 32) v += o;
            }
            if (lane == 0) s_ws[warp] = v;
        }
        __syncthreads();
        if (t < 8) {
            int wv = s_ws[t];
            #pragma unroll
            for (int off = 1; off < 8; off <<= 1) {
                int o = __shfl_down_sync(0xFFu, wv, off);
                if (t + off < 8) wv += o;
            }
            s_ws[t] = wv;
        }
        __syncthreads();
        if (t < 256)
            s_scan[t] = v + ((warp < 7) ? s_ws[warp + 1] : 0);   // suffix sums
        __syncthreads();
        if (t < 256) {
            int Sd  = s_scan[t];
            int Sd1 = (t == 255) ? 0 : s_scan[t + 1];
            if (Sd >= rem && Sd1 < rem) {          // unique crossing thread
                s_pref = pref | ((unsigned)t << shift);
                s_rem  = rem - Sd1;
                s_tot  = (MAXN - rem) + Sd;        // all candidates >= boundary
            }
        }
        __syncthreads();
        if (s_tot <= 256) { sh = shift; break; }
    }

    if (sh >= 0) {
        // ---- PATH A: collect all candidates >= truncated boundary, sort ----
        const unsigned th = s_pref >> sh;
        const int tot = s_tot;
        #pragma unroll
        for (int it = 0; it < NIT; it++) {
            unsigned bal = __ballot_sync(0xffffffffu, (u[it] >> sh) >= th);
            if (lane == 0) s_wc[it*NWARP + warp] = __popc(bal);
        }
        __syncthreads();
        if (t < 384) {
            int v = s_wc[t];
            #pragma unroll
            for (int off = 1; off < 32; off <<= 1) {
                int o = __shfl_up_sync(0xffffffffu, v, off);
                if (lane >= off) v += o;
            }
            s_scan[t] = v;
            if (lane == 31) s_ws[warp] = v;
        }
        __syncthreads();
        if (t < 12) {
            int wv = s_ws[t];
            #pragma unroll
            for (int off = 1; off < 16; off <<= 1) {
                int o = __shfl_up_sync(0xFFFu, wv, off);
                if (t >= off) wv += o;
            }
            s_ws[t] = wv;
        }
        __syncthreads();
        #pragma unroll
        for (int it = 0; it < NIT; it++) {
            bool pred = (u[it] >> sh) >= th;
            unsigned bal = __ballot_sync(0xffffffffu, pred);
            int cw = it*NWARP + warp;
            int widx = cw >> 5;
            int excl = s_scan[cw] + ((widx > 0) ? s_ws[widx - 1] : 0) - __popc(bal);
            if (pred) {
                int rank = excl + __popc(bal & ((1u << lane) - 1u));
                s_sel[rank] = (((ull)u[it]) << 32) | (unsigned)(~(unsigned)(it*TC + t));
            }
        }
        if (t >= tot && t < 256) s_sel[t] = 0ULL;
        __syncthreads();
    } else {
        // ---- PATH B (fallback): exact threshold + ordered tie collection ----
        const unsigned u_t = s_pref;
        const int ktie = s_rem;
        #pragma unroll
        for (int it = 0; it < NIT; it++) {
            unsigned bg = __ballot_sync(0xffffffffu, u[it] > u_t);
            unsigned bt = __ballot_sync(0xffffffffu, u[it] == u_t);
            if (lane == 0) s_wc[it*NWARP + warp] = (__popc(bg) << 16) | __popc(bt);
        }
        __syncthreads();
        if (t < 384) {
            int v = s_wc[t];
            #pragma unroll
            for (int off = 1; off < 32; off <<= 1) {
                int o = __shfl_up_sync(0xffffffffu, v, off);
                if (lane >= off) v += o;
            }
            s_scan[t] = v;
            if (lane == 31) s_ws[warp] = v;
        }
        __syncthreads();
        if (t < 12) {
            int wv = s_ws[t];
            #pragma unroll
            for (int off = 1; off < 16; off <<= 1) {
                int o = __shfl_up_sync(0xFFFu, wv, off);
                if (t >= off) wv += o;
            }
            s_ws[t] = wv;
        }
        __syncthreads();
        const int cG = s_ws[11] >> 16;
        #pragma unroll
        for (int it = 0; it < NIT; it++) {
            unsigned uu = u[it];
            bool g = (uu > u_t), e = (uu == u_t);
            unsigned bg = __ballot_sync(0xffffffffu, g);
            unsigned bt = __ballot_sync(0xffffffffu, e);
            int cw = it*NWARP + warp;
            int widx = cw >> 5;
            int incl = s_scan[cw] + ((widx > 0) ? s_ws[widx - 1] : 0);
            int excl = incl - ((__popc(bg) << 16) | __popc(bt));
            unsigned below = (1u << lane) - 1u;
            if (g) {
                int rank = (excl >> 16) + __popc(bg & below);
                s_sel[rank] = (((ull)uu) << 32) | (unsigned)(~(unsigned)(it*TC + t));
            }
            if (e) {
                int rank = (excl & 0xFFFF) + __popc(bt & below);
                if (rank < ktie)
                    s_sel[cG + rank] = (((ull)u_t) << 32) | (unsigned)(~(unsigned)(it*TC + t));
            }
        }
        if (t >= MAXN && t < 256) s_sel[t] = 0ULL;
        __syncthreads();
    }

    // ---- bitonic sort 256 keys descending (value desc, index asc) ----
    ull k = (t < 256) ? s_sel[t] : 0ULL;
    if (t < 256) {
        #pragma unroll
        for (int kk = 2; kk <= 32; kk <<= 1) {
            #pragma unroll
            for (int j = kk >> 1; j > 0; j >>= 1) {
                ull o = __shfl_xor_sync(0xffffffffu, k, j);
                bool takeMax = (((t & kk) == 0) != ((t & j) != 0));
                k = takeMax ? (k > o ? k : o) : (k < o ? k : o);
            }
        }
    }
    #pragma unroll
    for (int kk = 64; kk <= 256; kk <<= 1) {
        for (int j = kk >> 1; j >= 32; j >>= 1) {
            __syncthreads();
            if (t < 256) s_sel[t] = k;
            __syncthreads();
            if (t < 256) {
                ull o = s_sel[t ^ j];
                bool takeMax = (((t & kk) == 0) != ((t & j) != 0));
                k = takeMax ? (k > o ? k : o) : (k < o ? k : o);
            }
        }
        if (t < 256) {
            #pragma unroll
            for (int j = 16; j > 0; j >>= 1) {
                ull o = __shfl_xor_sync(0xffffffffu, k, j);
                bool takeMax = (((t & kk) == 0) != ((t & j) != 0));
                k = takeMax ? (k > o ? k : o) : (k < o ? k : o);
            }
        }
    }

    // ---- node features + export (x, y, valid) for the NN kernel ----
    const float REC63x2 = __uint_as_float(0x3D020821u);  // f32(1/63)*2
    if (t < MAXN) {
        unsigned idx = ~((unsigned)k);
        float rv = s_resp[idx];
        bool valid = (fabsf(rv) > 0.1f);
        int c  = idx >> 12;
        int rem2 = idx & 4095;
        int yi = rem2 >> 6, xi = rem2 & 63;
        float xc = __fsub_rn(__fmul_rn((float)xi, REC63x2), 1.0f);
        float yc = __fsub_rn(__fmul_rn((float)yi, REC63x2), 1.0f);
        float ecc = __fsqrt_rn(__fadd_rn(__fmul_rn(xc, xc), __fmul_rn(yc, yc)));
        float pol = (rv > 0.0f) ? 1.0f : ((rv < 0.0f) ? -1.0f : 0.0f);
        float vf = valid ? 1.0f : 0.0f;
        float* nrow = out + O_NODES + ((size_t)b*MAXN + t)*5;
        nrow[0] = xc * vf;
        nrow[1] = yc * vf;
        nrow[2] = pol * vf;
        nrow[3] = (float)c * vf;
        nrow[4] = ecc * vf;
        g_xy [b*MAXN + t] = make_float2(xc * vf, yc * vf);
        g_val[b*MAXN + t] = valid ? 1 : 0;
        out[O_NV + b*MAXN + t] = vf;
        out[O_BI + b*MAXN + t] = (float)b;
    }
}

// ============================================================
// Kernel 2: 6-NN + edges, one warp per node.  grid = (64, 13), 512 thr
// ============================================================
__global__ void __launch_bounds__(TN)
nn_kernel(float* __restrict__ out)
{
    __shared__ float2 s_xy[MAXN];
    __shared__ int s_val[MAXN];

    const int b = blockIdx.x;
    const int t = threadIdx.x;
    const int lane = t & 31, warp = t >> 5;

    if (t < MAXN) {
        int v = g_val[b*MAXN + t];
        float2 xy = g_xy[b*MAXN + t];
        s_val[t] = v;
        // sentinel coords for invalid nodes: distance becomes inf, sorts after
        // all real distances (like the reference's 1e9); those slots only ever
        // emit ev=0 -> all-zero outputs.
        s_xy[t] = v ? xy : make_float2(1e19f, 1e19f);
    }
    __syncthreads();

    const int node = blockIdx.y * (TN/32) + warp;
    if (node >= MAXN) return;

    const float2 p = s_xy[node];
    const int sv = s_val[node];

    // collect 7 raw keys; m=0..5 always in-range (lane+160 <= 191 < 196)
    ull key[7];
    #pragma unroll
    for (int m = 0; m < 6; m++) {
        int j = lane + m*32;
        float2 pj = s_xy[j];
        float dx = __fsub_rn(p.x, pj.x);
        float dy = __fsub_rn(p.y, pj.y);
        float s2 = __fadd_rn(__fmul_rn(dx, dx), __fmul_rn(dy, dy));
        float d = (s2 > 0.0f) ? __fsqrt_rn(s2) : 0.0f;
        if (j == node) d = 1000000000.0f;
        key[m] = (((ull)__float_as_uint(d)) << 32) | (unsigned)j;
    }
    {
        int j = lane + 192;
        if (j < MAXN) {
            float2 pj = s_xy[j];
            float dx = __fsub_rn(p.x, pj.x);
            float dy = __fsub_rn(p.y, pj.y);
            float s2 = __fadd_rn(__fmul_rn(dx, dx), __fmul_rn(dy, dy));
            float d = (s2 > 0.0f) ? __fsqrt_rn(s2) : 0.0f;
            if (j == node) d = 1000000000.0f;
            key[6] = (((ull)__float_as_uint(d)) << 32) | (unsigned)j;
        } else {
            key[6] = 0xFFFFFFFF00000000ULL;   // sorts after everything real
        }
    }

    // odd-even transposition sort of 7 keys (21 CAS)
    #pragma unroll
    for (int r = 0; r < 7; r++) {
        #pragma unroll
        for (int i = (r & 1); i + 1 < 7; i += 2) {
            ull a = key[i], c = key[i+1];
            key[i]   = (a < c) ? a : c;
            key[i+1] = (a < c) ? c : a;
        }
    }

    // 6-round tournament, 32-bit reductions (d >= 0 -> bits monotone unsigned)
    unsigned res_d = 0xFFFFFFFFu, res_j = 0;
    #pragma unroll
    for (int q = 0; q < KNBR; q++) {
        unsigned dh = (unsigned)(key[0] >> 32);
        unsigned jh = (unsigned)key[0];
        unsigned dmin = dh;
        #pragma unroll
        for (int off = 16; off > 0; off >>= 1) {
            unsigned o = __shfl_xor_sync(0xffffffffu, dmin, off);
            dmin = (o < dmin) ? o : dmin;
        }
        unsigned jm = (dh == dmin) ? jh : 0xFFFFFFFFu;
        #pragma unroll
        for (int off = 16; off > 0; off >>= 1) {
            unsigned o = __shfl_xor_sync(0xffffffffu, jm, off);
            jm = (o < jm) ? o : jm;
        }
        if (lane == q) { res_d = dmin; res_j = jm; }
        if (dh == dmin && jh == jm) {
            #pragma unroll
            for (int r = 0; r < 6; r++) key[r] = key[r+1];
            key[6] = 0xFFFFFFFFFFFFFFFFULL;
        }
    }

    // lanes 0..5 emit edges (select-masked: sentinel values never leak)
    if (lane < KNBR) {
        const float DIST_T = (float)(4.05 / 4.2);
        unsigned jd = res_j;
        float d = __uint_as_float(res_d);
        bool ev = (d < DIST_T) && (sv != 0);
        float2 pj = s_xy[jd];
        float dx = __fsub_rn(pj.x, p.x);
        float dy = __fsub_rn(pj.y, p.y);
        float s2 = __fadd_rn(__fmul_rn(dx, dx), __fmul_rn(dy, dy));
        float cd = (s2 > 0.0f) ? __fsqrt_rn(s2) : 0.0f;
        size_t e = ((size_t)b*MAXN + node)*KNBR + lane;
        out[O_EI + e]              = ev ? (float)(b*MAXN + node) : 0.0f;
        out[O_EI + N_EDGE_TOT + e] = ev ? (float)(b*MAXN + jd)   : 0.0f;
        out[O_EF + e*3 + 0] = ev ? dx : 0.0f;
        out[O_EF + e*3 + 1] = ev ? dy : 0.0f;
        out[O_EF + e*3 + 2] = ev ? cd : 0.0f;
        out[O_EV + e] = ev ? 1.0f : 0.0f;
    }
}

extern "C" void kernel_launch(void* const* d_in, const int* in_sizes, int n_in,
                              void* d_out, int out_size)
{
    const float* img = (const float*)d_in[0];
    const float* w1  = (const float*)d_in[1];
    const float* w2  = (const float*)d_in[2];
    const float* w3  = (const float*)d_in[3];
    float* out = (float*)d_out;

    cudaFuncSetAttribute(main_kernel,
                         cudaFuncAttributeMaxDynamicSharedMemorySize, SM_TOTAL);
    main_kernel<<<B, TC, SM_TOTAL>>>(img, w1, w2, w3, out);

    nn_kernel<<<dim3(B, (MAXN + TN/32 - 1) / (TN/32)), TN>>>(out);
}